// round 14
// baseline (speedup 1.0000x reference)
#include <cuda_runtime.h>
#include <cstdint>

#define NB    2
#define NPTS  16384
#define MC3   8192
#define NROI  128
#define NKP   2048
#define CBEV  256
#define CRAW  32
#define CC3   64
#define CF    (CBEV + CRAW + CC3)   // 352
#define COUT  128
#define HW    188
#define GRIDC 24
#define NCELL (GRIDC * GRIDC)       // 576
#define NCHK  1024                  // 16-point chunks
#define FULLM 0xffffffffu

typedef unsigned long long ull;

// monotonic float <-> uint key (total order; umax on key == fmax)
__device__ __forceinline__ unsigned fkey(float f) {
    unsigned b = __float_as_uint(f);
    return b ^ ((unsigned)((int)b >> 31) | 0x80000000u);
}

// f32x2 packed helpers (sm_103a) — per-lane IEEE identical to scalar
__device__ __forceinline__ ull f2pack(float lo, float hi) {
    ull r; asm("mov.b64 %0,{%1,%2};" : "=l"(r) : "f"(lo), "f"(hi)); return r;
}
__device__ __forceinline__ void f2unpack(ull v, float& lo, float& hi) {
    asm("mov.b64 {%0,%1},%2;" : "=f"(lo), "=f"(hi) : "l"(v));
}
__device__ __forceinline__ ull f2add(ull a, ull b) {
    ull r; asm("add.rn.f32x2 %0,%1,%2;" : "=l"(r) : "l"(a), "l"(b)); return r;
}
__device__ __forceinline__ ull f2mul(ull a, ull b) {
    ull r; asm("mul.rn.f32x2 %0,%1,%2;" : "=l"(r) : "l"(a), "l"(b)); return r;
}
__device__ __forceinline__ ull f2fma(ull a, ull b, ull c) {
    ull r; asm("fma.rn.f32x2 %0,%1,%2,%3;" : "=l"(r) : "l"(a), "l"(b), "l"(c)); return r;
}

// ---------------- scratch (device globals; no allocation allowed) -----------
__device__ float g_px[NB][NPTS], g_py[NB][NPTS], g_pz[NB][NPTS];
__device__ unsigned char g_valid[NB][NPTS];
__device__ unsigned short g_cell[NB][NPTS];
__device__ int g_nvalid[NB];
// pair-transposed coords: pair q (pts 2q,2q+1) of chunk c at [q*1024+c]
__device__ float2 g_txp[NB][8 * 1024];
__device__ float2 g_typ[NB][8 * 1024];
__device__ float2 g_tzp[NB][8 * 1024];
__device__ unsigned short g_perm[NB][NPTS];
__device__ float4 g_meta[NB][NCHK];
__device__ float g_cx[NB][MC3], g_cy[NB][MC3], g_cz[NB][MC3];
__device__ float g_kpx[NB][NKP], g_kpy[NB][NKP], g_kpz[NB][NKP];
__device__ float g_fraw[NB * NPTS * CRAW];
__device__ float g_fc3[NB * MC3 * CC3];
__device__ float g_feats[NB * NKP * CF];

// ---------------- 1) SoA copy + ROI validity + cell id ----------------------
__global__ void prep_points_kernel(const float* __restrict__ points,
                                   const float* __restrict__ bboxes) {
    int tid = blockIdx.x * blockDim.x + threadIdx.x;
    if (tid >= NB * NPTS) return;
    int b = tid / NPTS, i = tid % NPTS;
    const float* p = points + (size_t)tid * 5;
    float x = p[0], y = p[1], z = p[2];
    g_px[b][i] = x; g_py[b][i] = y; g_pz[b][i] = z;

    float best = 3.0e38f;
    int bidx = 0;
    const float* bb0 = bboxes + (size_t)b * NROI * 7;
    for (int r = 0; r < NROI; ++r) {
        const float* bb = bb0 + r * 7;
        float dx = x - bb[0], dy = y - bb[1], dz = z - bb[2];
        float d = __fsqrt_rn(dx * dx + dy * dy + dz * dz);
        if (d < best) { best = d; bidx = r; }
    }
    const float* bb = bb0 + bidx * 7;
    float hx = bb[3] * 0.5f, hy = bb[4] * 0.5f, hz = bb[5] * 0.5f;
    float rm = __fsqrt_rn(hx * hx + hy * hy + hz * hz);
    g_valid[b][i] = (best < rm + 2.4f) ? 1 : 0;

    const float inv = (float)GRIDC / 150.4f;
    int cx = min(GRIDC - 1, max(0, (int)((x + 75.2f) * inv)));
    int cy = min(GRIDC - 1, max(0, (int)((y + 75.2f) * inv)));
    g_cell[b][i] = (unsigned short)(cy * GRIDC + cx);
}

// ---------------- 2) fused hist+scan+scatter+bounds (1 block/batch) ---------
__global__ void __launch_bounds__(1024, 1) sortprep_kernel() {
    __shared__ int h[NCELL];
    __shared__ int sa[NCELL], sb[NCELL];
    __shared__ int cur[NCELL];
    __shared__ int s_n;
    int b = blockIdx.x, t = threadIdx.x;

    if (t < NCELL) h[t] = 0;
    for (int i = t; i < 8 * 1024; i += 1024) {
        g_txp[b][i] = make_float2(0.0f, 0.0f);
        g_typ[b][i] = make_float2(0.0f, 0.0f);
        g_tzp[b][i] = make_float2(0.0f, 0.0f);
    }
    __syncthreads();
    for (int i = t; i < NPTS; i += 1024)
        if (g_valid[b][i]) atomicAdd(&h[g_cell[b][i]], 1);
    __syncthreads();
    if (t < NCELL) sa[t] = h[t];
    __syncthreads();
    int* src = sa; int* dst = sb;
    for (int off = 1; off < NCELL; off <<= 1) {
        int v = 0;
        if (t < NCELL) { v = src[t]; if (t >= off) v += src[t - off]; }
        __syncthreads();
        if (t < NCELL) dst[t] = v;
        __syncthreads();
        int* tmp = src; src = dst; dst = tmp;
    }
    if (t < NCELL) cur[t] = src[t] - h[t];
    if (t == NCELL - 1) { s_n = src[t]; g_nvalid[b] = src[t]; }
    __syncthreads();

    // scatter into pair-transposed sorted order
    for (int i = t; i < NPTS; i += 1024) {
        if (g_valid[b][i]) {
            int cell = g_cell[b][i];
            int pos = atomicAdd(&cur[cell], 1);
            int c = pos >> 4, p = pos & 15;
            int fidx = ((p >> 1) * 1024 + c) * 2 + (p & 1);
            ((float*)g_txp[b])[fidx] = g_px[b][i];
            ((float*)g_typ[b])[fidx] = g_py[b][i];
            ((float*)g_tzp[b])[fidx] = g_pz[b][i];
            g_perm[b][pos] = (unsigned short)i;
        }
    }
    __syncthreads();   // block-scope fence: scatter writes visible below

    // per-chunk bounding spheres (thread t owns 16-pt chunk t)
    {
        int n = s_n;
        int sz = min(16, n - 16 * t);
        float4 out;
        if (sz <= 0) {
            out = make_float4(1.0e8f, 1.0e8f, 1.0e8f, 0.0f);
        } else {
            float xn = 3.0e38f, xm = -3.0e38f;
            float yn = 3.0e38f, ym = -3.0e38f;
            float zn = 3.0e38f, zm = -3.0e38f;
            for (int p = 0; p < sz; ++p) {
                int fidx = ((p >> 1) * 1024 + t) * 2 + (p & 1);
                float x = ((const float*)g_txp[b])[fidx];
                float y = ((const float*)g_typ[b])[fidx];
                float z = ((const float*)g_tzp[b])[fidx];
                xn = fminf(xn, x); xm = fmaxf(xm, x);
                yn = fminf(yn, y); ym = fmaxf(ym, y);
                zn = fminf(zn, z); zm = fmaxf(zm, z);
            }
            float ccx = (xn + xm) * 0.5f, ccy = (yn + ym) * 0.5f, ccz = (zn + zm) * 0.5f;
            float m2 = 0.0f;
            for (int p = 0; p < sz; ++p) {
                int fidx = ((p >> 1) * 1024 + t) * 2 + (p & 1);
                float dx = ((const float*)g_txp[b])[fidx] - ccx;
                float dy = ((const float*)g_typ[b])[fidx] - ccy;
                float dz = ((const float*)g_tzp[b])[fidx] - ccz;
                m2 = fmaxf(m2, dx * dx + dy * dy + dz * dz);
            }
            float r = __fsqrt_rn(m2);
            out = make_float4(ccx, ccy, ccz, r * 1.00002f + 1.0e-3f);
        }
        g_meta[b][t] = out;
    }
}

// ---------------- 3) conv3 SoA copy ------------------------------------------
__global__ void prep_c3_kernel(const float* __restrict__ conv3) {
    int tid = blockIdx.x * blockDim.x + threadIdx.x;
    if (tid >= NB * MC3) return;
    int b = tid / MC3, i = tid % MC3;
    const float* p = conv3 + (size_t)tid * 67;
    g_cx[b][i] = p[0]; g_cy[b][i] = p[1]; g_cz[b][i] = p[2];
}

// ---------------- 4) FPS: 1024 threads, 16-pt chunk/thread, f32x2 update ----
// Thread t owns chunk t (sorted pts 16t..16t+15). Coords in smem as point-
// pairs (f32x2-ready, conflict-free). dd[16] static registers; perm NOT in
// registers (rare __ldg on rescan match) -> no spill at the 64-reg cap.
// Persistent s_pairs[32]; every warp redundantly block-reduces (one REDUX
// pass over 32 slots); only changed warps re-reduce their slot; ONE barrier.
// Pair = fkey(chunkmax)<<32 | (0x3fff - minorig)<<14 | sortedpos
//  == (max value, then min ORIGINAL index) == jnp.argmax. f32x2 distance
//  math is per-lane identical to scalar (validated R1: same rel_err).
__global__ void __launch_bounds__(1024, 1) fps_kernel() {
    extern __shared__ float smem[];
    float2* s_xp = (float2*)smem;                // [8][1024] pairs
    float2* s_yp = (float2*)smem + 8 * 1024;
    float2* s_zp = (float2*)smem + 16 * 1024;
    __shared__ ull s_pairs[32];

    int b = blockIdx.x, t = threadIdx.x;
    int w = t >> 5, j = t & 31;
    int n = g_nvalid[b];
    const unsigned short* perm = g_perm[b];

    {
        const float* gx = (const float*)g_txp[b];
        const float* gy = (const float*)g_typ[b];
        const float* gz = (const float*)g_tzp[b];
        float* sx = smem;
        float* sy = smem + 16384;
        float* sz = smem + 32768;
        for (int i = t; i < NPTS; i += 1024) {
            sx[i] = gx[i]; sy[i] = gy[i]; sz[i] = gz[i];
        }
    }
    float4 mt = g_meta[b][t];

    float dd[16];
    #pragma unroll
    for (int p = 0; p < 16; ++p)
        dd[p] = (16 * t + p < n) ? 1.0e10f : -1.0e10f;

    // initial pair (scan all 16; one-time)
    float vm = dd[0];
    #pragma unroll
    for (int p = 1; p < 16; ++p) vm = fmaxf(vm, dd[p]);
    unsigned bo = 0xffffu; int bp = 0;
    #pragma unroll
    for (int p = 0; p < 16; ++p) {
        if (dd[p] == vm) {
            unsigned o = __ldg(perm + 16 * t + p);
            if (o < bo) { bo = o; bp = p; }
        }
    }
    ull pair = ((ull)fkey(vm) << 32)
             | ((ull)((0x3fffu - bo) & 0x3fffu) << 14)
             | (ull)(16 * t + bp);
    {
        unsigned hk = (unsigned)(pair >> 32);
        unsigned wk = __reduce_max_sync(FULLM, hk);
        unsigned lo = (hk == wk) ? (unsigned)pair : 0u;
        lo = __reduce_max_sync(FULLM, lo);
        if (j == 0) s_pairs[w] = ((ull)wk << 32) | lo;
    }
    __syncthreads();

    for (int it = 0; it < NKP; ++it) {
        // ---- redundant block reduce (32 slots == 32 lanes, one pass) ----
        ull p2 = s_pairs[j];
        unsigned hk2 = (unsigned)(p2 >> 32);
        unsigned wk2 = __reduce_max_sync(FULLM, hk2);
        unsigned lo2 = (hk2 == wk2) ? (unsigned)p2 : 0u;
        lo2 = __reduce_max_sync(FULLM, lo2);
        int sp = (int)(lo2 & 0x3fffu);
        int c = sp >> 4, pp = sp & 15;
        int pi = (pp >> 1) * 1024 + c;
        int h = pp & 1;
        float2 xv = s_xp[pi], yv = s_yp[pi], zv = s_zp[pi];
        float kx = h ? xv.y : xv.x;
        float ky = h ? yv.y : yv.x;
        float kz = h ? zv.y : zv.x;
        if (t == 0) { g_kpx[b][it] = kx; g_kpy[b][it] = ky; g_kpz[b][it] = kz; }
        if (it == NKP - 1) break;

        // ---- pruned update (f32x2 packed; per-lane == scalar) ----
        float dxc = kx - mt.x, dyc = ky - mt.y, dzc = kz - mt.z;
        float dc = __fsqrt_rn(dxc * dxc + dyc * dyc + dzc * dzc);
        float lhs = dc - mt.w - 1.0e-3f;
        bool changed = !((lhs > 0.0f) && (lhs * lhs * 0.99999f > vm));
        if (changed) {
            ull knx = f2pack(-kx, -kx);
            ull kny = f2pack(-ky, -ky);
            ull knz = f2pack(-kz, -kz);
            float m0 = -3.0e38f, m1 = -3.0e38f;
            #pragma unroll
            for (int q = 0; q < 8; ++q) {
                int ti = q * 1024 + t;
                float2 xq = s_xp[ti], yq = s_yp[ti], zq = s_zp[ti];
                ull dx = f2add(f2pack(xq.x, xq.y), knx);
                ull dy = f2add(f2pack(yq.x, yq.y), kny);
                ull dz = f2add(f2pack(zq.x, zq.y), knz);
                ull d2 = f2mul(dx, dx);
                d2 = f2fma(dy, dy, d2);
                d2 = f2fma(dz, dz, d2);
                float n0, n1; f2unpack(d2, n0, n1);
                float v0 = fminf(dd[2 * q],     n0);
                float v1 = fminf(dd[2 * q + 1], n1);
                dd[2 * q] = v0; dd[2 * q + 1] = v1;
                if (q < 4) { m0 = fmaxf(m0, fmaxf(v0, v1)); }
                else       { m1 = fmaxf(m1, fmaxf(v0, v1)); }
            }
            vm = fmaxf(m0, m1);
            unsigned nbo = 0xffffu; int nbp = 0;
            if (m0 == vm) {
                #pragma unroll
                for (int p = 0; p < 8; ++p)
                    if (dd[p] == vm) {
                        unsigned o = __ldg(perm + 16 * t + p);
                        if (o < nbo) { nbo = o; nbp = p; }
                    }
            }
            if (m1 == vm) {
                #pragma unroll
                for (int p = 8; p < 16; ++p)
                    if (dd[p] == vm) {
                        unsigned o = __ldg(perm + 16 * t + p);
                        if (o < nbo) { nbo = o; nbp = p; }
                    }
            }
            pair = ((ull)fkey(vm) << 32)
                 | ((ull)((0x3fffu - nbo) & 0x3fffu) << 14)
                 | (ull)(16 * t + nbp);
        }
        if (__ballot_sync(FULLM, changed)) {
            unsigned hk = (unsigned)(pair >> 32);
            unsigned wk = __reduce_max_sync(FULLM, hk);
            unsigned lo = (hk == wk) ? (unsigned)pair : 0u;
            lo = __reduce_max_sync(FULLM, lo);
            if (j == 0) s_pairs[w] = ((ull)wk << 32) | lo;
        }
        __syncthreads();                               // the ONLY barrier
    }
}

// ---------------- 5) per-point MLPs -----------------------------------------
__global__ void fraw_kernel(const float* __restrict__ points,
                            const float* __restrict__ W,
                            const float* __restrict__ bias) {
    int tid = blockIdx.x * blockDim.x + threadIdx.x;
    if (tid >= NB * NPTS * CRAW) return;
    int c = tid & (CRAW - 1);
    int pi = tid >> 5;
    const float* p = points + (size_t)pi * 5;
    float v = p[3] * W[c] + p[4] * W[CRAW + c] + bias[c];
    g_fraw[tid] = fmaxf(v, 0.0f);
}

__global__ void fc3_kernel(const float* __restrict__ conv3,
                           const float* __restrict__ W,
                           const float* __restrict__ bias) {
    int tid = blockIdx.x * blockDim.x + threadIdx.x;
    if (tid >= NB * MC3 * CC3) return;
    int c = tid & (CC3 - 1);
    int pi = tid >> 6;
    const float* p = conv3 + (size_t)pi * 67 + 3;
    float acc = 0.0f;
    #pragma unroll 8
    for (int k = 0; k < CC3; ++k) acc += p[k] * W[k * CC3 + c];
    g_fc3[tid] = fmaxf(acc + bias[c], 0.0f);
}

// ---------------- 6) bilinear BEV sampling ----------------------------------
__global__ void bev_kernel(const float* __restrict__ sf) {
    int k = blockIdx.x, b = blockIdx.y, c = threadIdx.x;
    float kx = g_kpx[b][k], ky = g_kpy[b][k];
    float xi = __fdiv_rn(__fdiv_rn(kx - (-75.2f), 0.1f), 8.0f);
    float yi = __fdiv_rn(__fdiv_rn(ky - (-75.2f), 0.1f), 8.0f);
    int x0 = min(max((int)floorf(xi), 0), HW - 1);
    int x1 = min(x0 + 1, HW - 1);
    int y0 = min(max((int)floorf(yi), 0), HW - 1);
    int y1 = min(y0 + 1, HW - 1);
    float xf0 = (float)x0, xf1 = (float)x1, yf0 = (float)y0, yf1 = (float)y1;
    float wa = (xf1 - xi) * (yf1 - yi);
    float wb = (xf1 - xi) * (yi - yf0);
    float wc = (xi - xf0) * (yf1 - yi);
    float wd = (xi - xf0) * (yi - yf0);
    const float* im = sf + ((size_t)b * CBEV + c) * (HW * HW);
    float Ia = im[y0 * HW + x0];
    float Ib = im[y1 * HW + x0];
    float Ic = im[y0 * HW + x1];
    float Id = im[y1 * HW + x1];
    g_feats[((size_t)b * NKP + k) * CF + c] = Ia * wa + Ib * wb + Ic * wc + Id * wd;
}

// ---------------- 7) radius aggregation (ballot-broadcast) ------------------
__global__ void agg_raw_kernel(float r2) {
    int b = blockIdx.y;
    int warp = threadIdx.x >> 5, lane = threadIdx.x & 31;
    int k = blockIdx.x * 8 + warp;
    float kx = g_kpx[b][k], ky = g_kpy[b][k], kz = g_kpz[b][k];
    float acc = 0.0f;
    int cnt = 0;
    __shared__ float sx[256], sy[256], sz[256];
    for (int base = 0; base < NPTS; base += 256) {
        __syncthreads();
        int i = base + threadIdx.x;
        sx[threadIdx.x] = g_px[b][i];
        sy[threadIdx.x] = g_py[b][i];
        sz[threadIdx.x] = g_pz[b][i];
        __syncthreads();
        #pragma unroll
        for (int s = 0; s < 8; ++s) {
            int jj = s * 32 + lane;
            float dx = sx[jj] - kx, dy = sy[jj] - ky, dz = sz[jj] - kz;
            float d2 = dx * dx + dy * dy + dz * dz;
            unsigned m = __ballot_sync(FULLM, d2 < r2);
            while (m) {
                int src = __ffs(m) - 1;
                m &= m - 1;
                int gp = base + s * 32 + src;
                acc += g_fraw[((size_t)b * NPTS + gp) * CRAW + lane];
                cnt++;
            }
        }
    }
    float c = fmaxf((float)cnt, 1.0f);
    g_feats[((size_t)b * NKP + k) * CF + CBEV + lane] = acc / c;
}

__global__ void agg_c3_kernel(float r2) {
    int b = blockIdx.y;
    int warp = threadIdx.x >> 5, lane = threadIdx.x & 31;
    int k = blockIdx.x * 8 + warp;
    float kx = g_kpx[b][k], ky = g_kpy[b][k], kz = g_kpz[b][k];
    float acc0 = 0.0f, acc1 = 0.0f;
    int cnt = 0;
    __shared__ float sx[256], sy[256], sz[256];
    for (int base = 0; base < MC3; base += 256) {
        __syncthreads();
        int i = base + threadIdx.x;
        sx[threadIdx.x] = g_cx[b][i];
        sy[threadIdx.x] = g_cy[b][i];
        sz[threadIdx.x] = g_cz[b][i];
        __syncthreads();
        #pragma unroll
        for (int s = 0; s < 8; ++s) {
            int jj = s * 32 + lane;
            float dx = sx[jj] - kx, dy = sy[jj] - ky, dz = sz[jj] - kz;
            float d2 = dx * dx + dy * dy + dz * dz;
            unsigned m = __ballot_sync(FULLM, d2 < r2);
            while (m) {
                int src = __ffs(m) - 1;
                m &= m - 1;
                int gp = base + s * 32 + src;
                const float* fp = g_fc3 + ((size_t)b * MC3 + gp) * CC3;
                acc0 += fp[lane];
                acc1 += fp[lane + 32];
                cnt++;
            }
        }
    }
    float c = fmaxf((float)cnt, 1.0f);
    float* o = g_feats + ((size_t)b * NKP + k) * CF + CBEV + CRAW;
    o[lane] = acc0 / c;
    o[lane + 32] = acc1 / c;
}

// ---------------- 8) fuse GEMM + BN + ReLU ----------------------------------
#define ROWS_PB 16
__global__ void fuse_kernel(const float* __restrict__ W,
                            const float* __restrict__ gamma,
                            const float* __restrict__ beta,
                            const float* __restrict__ mean,
                            const float* __restrict__ var,
                            float* __restrict__ out) {
    __shared__ float sf[ROWS_PB][CF];
    int row0 = blockIdx.x * ROWS_PB;
    int tid = threadIdx.x;
    for (int idx = tid; idx < ROWS_PB * CF; idx += 128) {
        ((float*)sf)[idx] = g_feats[(size_t)row0 * CF + idx];
    }
    __syncthreads();
    int c = tid;
    float acc[ROWS_PB];
    #pragma unroll
    for (int r = 0; r < ROWS_PB; ++r) acc[r] = 0.0f;
    for (int k = 0; k < CF; ++k) {
        float wv = W[k * COUT + c];
        #pragma unroll
        for (int r = 0; r < ROWS_PB; ++r) acc[r] += sf[r][k] * wv;
    }
    float mu = mean[c];
    float iv = rsqrtf(var[c] + 1e-5f);
    float g = gamma[c], be = beta[c];
    #pragma unroll
    for (int r = 0; r < ROWS_PB; ++r) {
        float v = (acc[r] - mu) * iv * g + be;
        out[(size_t)(row0 + r) * COUT + c] = fmaxf(v, 0.0f);
    }
}

// ---------------- 9) keypoints output ---------------------------------------
__global__ void kpout_kernel(float* __restrict__ out) {
    int tid = blockIdx.x * blockDim.x + threadIdx.x;
    if (tid >= NB * NKP * 3) return;
    int b = tid / (NKP * 3);
    int rem = tid % (NKP * 3);
    int k = rem / 3, d = rem % 3;
    float v = (d == 0) ? g_kpx[b][k] : (d == 1 ? g_kpy[b][k] : g_kpz[b][k]);
    out[(size_t)NB * NKP * COUT + tid] = v;
}

// ---------------- launcher ---------------------------------------------------
extern "C" void kernel_launch(void* const* d_in, const int* in_sizes, int n_in,
                              void* d_out, int out_size) {
    const float* points  = (const float*)d_in[0];
    const float* bboxes  = (const float*)d_in[1];
    const float* spatial = (const float*)d_in[2];
    const float* conv3   = (const float*)d_in[3];
    const float* W_raw   = (const float*)d_in[4];
    const float* b_raw   = (const float*)d_in[5];
    const float* W_c3    = (const float*)d_in[6];
    const float* b_c3    = (const float*)d_in[7];
    const float* W_fuse  = (const float*)d_in[8];
    const float* bn_g    = (const float*)d_in[9];
    const float* bn_b    = (const float*)d_in[10];
    const float* bn_m    = (const float*)d_in[11];
    const float* bn_v    = (const float*)d_in[12];
    float* out = (float*)d_out;

    const int fps_smem = 3 * NPTS * (int)sizeof(float);   // 196608 B
    cudaFuncSetAttribute(fps_kernel, cudaFuncAttributeMaxDynamicSharedMemorySize,
                         fps_smem);

    prep_points_kernel<<<(NB * NPTS + 255) / 256, 256>>>(points, bboxes);   // 1
    sortprep_kernel<<<NB, 1024>>>();                                        // 2
    prep_c3_kernel<<<(NB * MC3 + 255) / 256, 256>>>(conv3);                 // 3
    fps_kernel<<<NB, 1024, fps_smem>>>();                                   // 4 <- ncu
    fraw_kernel<<<(NB * NPTS * CRAW + 255) / 256, 256>>>(points, W_raw, b_raw);
    fc3_kernel<<<(NB * MC3 * CC3 + 255) / 256, 256>>>(conv3, W_c3, b_c3);
    bev_kernel<<<dim3(NKP, NB), CBEV>>>(spatial);
    agg_raw_kernel<<<dim3(NKP / 8, NB), 256>>>(0.8f * 0.8f);
    agg_c3_kernel<<<dim3(NKP / 8, NB), 256>>>(1.6f * 1.6f);
    fuse_kernel<<<(NB * NKP) / ROWS_PB, COUT>>>(W_fuse, bn_g, bn_b, bn_m, bn_v, out);
    kpout_kernel<<<(NB * NKP * 3 + 255) / 256, 256>>>(out);
}

// round 15
// speedup vs baseline: 1.0316x; 1.0316x over previous
#include <cuda_runtime.h>
#include <cstdint>

#define NB    2
#define NPTS  16384
#define MC3   8192
#define NROI  128
#define NKP   2048
#define CBEV  256
#define CRAW  32
#define CC3   64
#define CF    (CBEV + CRAW + CC3)   // 352
#define COUT  128
#define HW    188
#define GRIDC 24
#define NCELL (GRIDC * GRIDC)       // 576
#define NCHK  1024                  // 16-point chunks
#define FULLM 0xffffffffu

typedef unsigned long long ull;

// monotonic float <-> uint key (total order; umax on key == fmax)
__device__ __forceinline__ unsigned fkey(float f) {
    unsigned b = __float_as_uint(f);
    return b ^ ((unsigned)((int)b >> 31) | 0x80000000u);
}

// f32x2 packed helpers (sm_103a) — per-lane IEEE identical to scalar
__device__ __forceinline__ ull f2pack(float lo, float hi) {
    ull r; asm("mov.b64 %0,{%1,%2};" : "=l"(r) : "f"(lo), "f"(hi)); return r;
}
__device__ __forceinline__ void f2unpack(ull v, float& lo, float& hi) {
    asm("mov.b64 {%0,%1},%2;" : "=f"(lo), "=f"(hi) : "l"(v));
}
__device__ __forceinline__ ull f2add(ull a, ull b) {
    ull r; asm("add.rn.f32x2 %0,%1,%2;" : "=l"(r) : "l"(a), "l"(b)); return r;
}
__device__ __forceinline__ ull f2mul(ull a, ull b) {
    ull r; asm("mul.rn.f32x2 %0,%1,%2;" : "=l"(r) : "l"(a), "l"(b)); return r;
}
__device__ __forceinline__ ull f2fma(ull a, ull b, ull c) {
    ull r; asm("fma.rn.f32x2 %0,%1,%2,%3;" : "=l"(r) : "l"(a), "l"(b), "l"(c)); return r;
}

// ---------------- scratch (device globals; no allocation allowed) -----------
__device__ float g_px[NB][NPTS], g_py[NB][NPTS], g_pz[NB][NPTS];
__device__ unsigned char g_valid[NB][NPTS];
__device__ unsigned short g_cell[NB][NPTS];
__device__ int g_nvalid[NB];
// pair-transposed coords: pair q (pts 2q,2q+1) of chunk c at [q*1024+c]
__device__ float2 g_txp[NB][8 * 1024];
__device__ float2 g_typ[NB][8 * 1024];
__device__ float2 g_tzp[NB][8 * 1024];
__device__ unsigned short g_perm[NB][NPTS];
__device__ float4 g_meta[NB][NCHK];
__device__ float g_cx[NB][MC3], g_cy[NB][MC3], g_cz[NB][MC3];
__device__ float g_kpx[NB][NKP], g_kpy[NB][NKP], g_kpz[NB][NKP];
__device__ float g_fraw[NB * NPTS * CRAW];
__device__ float g_fc3[NB * MC3 * CC3];
__device__ float g_feats[NB * NKP * CF];

// ---------------- 1) SoA copy + ROI validity + cell id + pad zero-fill ------
__global__ void prep_points_kernel(const float* __restrict__ points,
                                   const float* __restrict__ bboxes) {
    int tid = blockIdx.x * blockDim.x + threadIdx.x;
    if (tid >= NB * NPTS) return;
    int b = tid / NPTS, i = tid % NPTS;
    // zero-fill transposed arrays (pad safety) -- runs on 128 blocks (free)
    ((float*)g_txp[b])[i] = 0.0f;
    ((float*)g_typ[b])[i] = 0.0f;
    ((float*)g_tzp[b])[i] = 0.0f;

    const float* p = points + (size_t)tid * 5;
    float x = p[0], y = p[1], z = p[2];
    g_px[b][i] = x; g_py[b][i] = y; g_pz[b][i] = z;

    float best = 3.0e38f;
    int bidx = 0;
    const float* bb0 = bboxes + (size_t)b * NROI * 7;
    for (int r = 0; r < NROI; ++r) {
        const float* bb = bb0 + r * 7;
        float dx = x - bb[0], dy = y - bb[1], dz = z - bb[2];
        float d = __fsqrt_rn(dx * dx + dy * dy + dz * dz);
        if (d < best) { best = d; bidx = r; }
    }
    const float* bb = bb0 + bidx * 7;
    float hx = bb[3] * 0.5f, hy = bb[4] * 0.5f, hz = bb[5] * 0.5f;
    float rm = __fsqrt_rn(hx * hx + hy * hy + hz * hz);
    g_valid[b][i] = (best < rm + 2.4f) ? 1 : 0;

    const float inv = (float)GRIDC / 150.4f;
    int cx = min(GRIDC - 1, max(0, (int)((x + 75.2f) * inv)));
    int cy = min(GRIDC - 1, max(0, (int)((y + 75.2f) * inv)));
    g_cell[b][i] = (unsigned short)(cy * GRIDC + cx);
}

// ---------------- 2) fused hist+scan+scatter+bounds (1 block/batch) ---------
__global__ void __launch_bounds__(1024, 1) sortprep_kernel() {
    __shared__ int h[NCELL];
    __shared__ int sa[NCELL], sb[NCELL];
    __shared__ int cur[NCELL];
    __shared__ int s_n;
    int b = blockIdx.x, t = threadIdx.x;

    if (t < NCELL) h[t] = 0;
    __syncthreads();
    for (int i = t; i < NPTS; i += 1024)
        if (g_valid[b][i]) atomicAdd(&h[g_cell[b][i]], 1);
    __syncthreads();
    if (t < NCELL) sa[t] = h[t];
    __syncthreads();
    int* src = sa; int* dst = sb;
    for (int off = 1; off < NCELL; off <<= 1) {
        int v = 0;
        if (t < NCELL) { v = src[t]; if (t >= off) v += src[t - off]; }
        __syncthreads();
        if (t < NCELL) dst[t] = v;
        __syncthreads();
        int* tmp = src; src = dst; dst = tmp;
    }
    if (t < NCELL) cur[t] = src[t] - h[t];
    if (t == NCELL - 1) { s_n = src[t]; g_nvalid[b] = src[t]; }
    __syncthreads();

    // scatter into pair-transposed sorted order
    for (int i = t; i < NPTS; i += 1024) {
        if (g_valid[b][i]) {
            int cell = g_cell[b][i];
            int pos = atomicAdd(&cur[cell], 1);
            int c = pos >> 4, p = pos & 15;
            int fidx = ((p >> 1) * 1024 + c) * 2 + (p & 1);
            ((float*)g_txp[b])[fidx] = g_px[b][i];
            ((float*)g_typ[b])[fidx] = g_py[b][i];
            ((float*)g_tzp[b])[fidx] = g_pz[b][i];
            g_perm[b][pos] = (unsigned short)i;
        }
    }
    __syncthreads();   // block-scope fence: scatter writes visible below

    // per-chunk bounding spheres (thread t owns 16-pt chunk t)
    {
        int n = s_n;
        int sz = min(16, n - 16 * t);
        float4 out;
        if (sz <= 0) {
            out = make_float4(1.0e8f, 1.0e8f, 1.0e8f, 0.0f);
        } else {
            float xn = 3.0e38f, xm = -3.0e38f;
            float yn = 3.0e38f, ym = -3.0e38f;
            float zn = 3.0e38f, zm = -3.0e38f;
            for (int p = 0; p < sz; ++p) {
                int fidx = ((p >> 1) * 1024 + t) * 2 + (p & 1);
                float x = ((const float*)g_txp[b])[fidx];
                float y = ((const float*)g_typ[b])[fidx];
                float z = ((const float*)g_tzp[b])[fidx];
                xn = fminf(xn, x); xm = fmaxf(xm, x);
                yn = fminf(yn, y); ym = fmaxf(ym, y);
                zn = fminf(zn, z); zm = fmaxf(zm, z);
            }
            float ccx = (xn + xm) * 0.5f, ccy = (yn + ym) * 0.5f, ccz = (zn + zm) * 0.5f;
            float m2 = 0.0f;
            for (int p = 0; p < sz; ++p) {
                int fidx = ((p >> 1) * 1024 + t) * 2 + (p & 1);
                float dx = ((const float*)g_txp[b])[fidx] - ccx;
                float dy = ((const float*)g_typ[b])[fidx] - ccy;
                float dz = ((const float*)g_tzp[b])[fidx] - ccz;
                m2 = fmaxf(m2, dx * dx + dy * dy + dz * dz);
            }
            float r = __fsqrt_rn(m2);
            out = make_float4(ccx, ccy, ccz, r * 1.00002f + 1.0e-3f);
        }
        g_meta[b][t] = out;
    }
}

// ---------------- 3) conv3 SoA copy ------------------------------------------
__global__ void prep_c3_kernel(const float* __restrict__ conv3) {
    int tid = blockIdx.x * blockDim.x + threadIdx.x;
    if (tid >= NB * MC3) return;
    int b = tid / MC3, i = tid % MC3;
    const float* p = conv3 + (size_t)tid * 67;
    g_cx[b][i] = p[0]; g_cy[b][i] = p[1]; g_cz[b][i] = p[2];
}

// ---------------- 4) FPS: keypoints staged in SMEM (no in-loop STG) ---------
// Thread t owns chunk t (sorted pts 16t..16t+15). Coords in smem as point-
// pairs (f32x2-ready, conflict-free). dd[16] static registers; perm via rare
// __ldg. Persistent s_pairs[32]; every warp redundantly block-reduces; only
// changed warps re-reduce their slot; ONE barrier per iteration.
// KEY CHANGE: per-iteration keypoint goes to SHARED memory (STS, cheap drain
// at the barrier) instead of global (STG drain suspected ~200-400 cyc/iter);
// global keypoint arrays written once, cooperatively, after the loop.
// Pair = fkey(chunkmax)<<32 | (0x3fff - minorig)<<14 | sortedpos
//  == (max value, then min ORIGINAL index) == jnp.argmax.
__global__ void __launch_bounds__(1024, 1) fps_kernel() {
    extern __shared__ float smem[];
    float2* s_xp = (float2*)smem;                // [8][1024] pairs
    float2* s_yp = (float2*)smem + 8 * 1024;
    float2* s_zp = (float2*)smem + 16 * 1024;
    float* s_kpx = smem + 3 * NPTS;              // [2048]
    float* s_kpy = smem + 3 * NPTS + NKP;
    float* s_kpz = smem + 3 * NPTS + 2 * NKP;
    __shared__ ull s_pairs[32];

    int b = blockIdx.x, t = threadIdx.x;
    int w = t >> 5, j = t & 31;
    int n = g_nvalid[b];
    const unsigned short* perm = g_perm[b];

    {
        const float* gx = (const float*)g_txp[b];
        const float* gy = (const float*)g_typ[b];
        const float* gz = (const float*)g_tzp[b];
        float* sx = smem;
        float* sy = smem + 16384;
        float* sz = smem + 32768;
        for (int i = t; i < NPTS; i += 1024) {
            sx[i] = gx[i]; sy[i] = gy[i]; sz[i] = gz[i];
        }
    }
    float4 mt = g_meta[b][t];

    float dd[16];
    #pragma unroll
    for (int p = 0; p < 16; ++p)
        dd[p] = (16 * t + p < n) ? 1.0e10f : -1.0e10f;

    // initial pair (scan all 16; one-time)
    float vm = dd[0];
    #pragma unroll
    for (int p = 1; p < 16; ++p) vm = fmaxf(vm, dd[p]);
    unsigned bo = 0xffffu; int bp = 0;
    #pragma unroll
    for (int p = 0; p < 16; ++p) {
        if (dd[p] == vm) {
            unsigned o = __ldg(perm + 16 * t + p);
            if (o < bo) { bo = o; bp = p; }
        }
    }
    ull pair = ((ull)fkey(vm) << 32)
             | ((ull)((0x3fffu - bo) & 0x3fffu) << 14)
             | (ull)(16 * t + bp);
    {
        unsigned hk = (unsigned)(pair >> 32);
        unsigned wk = __reduce_max_sync(FULLM, hk);
        unsigned lo = (hk == wk) ? (unsigned)pair : 0u;
        lo = __reduce_max_sync(FULLM, lo);
        if (j == 0) s_pairs[w] = ((ull)wk << 32) | lo;
    }
    __syncthreads();

    for (int it = 0; it < NKP; ++it) {
        // ---- redundant block reduce (32 slots == 32 lanes, one pass) ----
        ull p2 = s_pairs[j];
        unsigned hk2 = (unsigned)(p2 >> 32);
        unsigned wk2 = __reduce_max_sync(FULLM, hk2);
        unsigned lo2 = (hk2 == wk2) ? (unsigned)p2 : 0u;
        lo2 = __reduce_max_sync(FULLM, lo2);
        int sp = (int)(lo2 & 0x3fffu);
        int c = sp >> 4, pp = sp & 15;
        int pi = (pp >> 1) * 1024 + c;
        int h = pp & 1;
        float2 xv = s_xp[pi], yv = s_yp[pi], zv = s_zp[pi];
        float kx = h ? xv.y : xv.x;
        float ky = h ? yv.y : yv.x;
        float kz = h ? zv.y : zv.x;
        if (t == 0) { s_kpx[it] = kx; s_kpy[it] = ky; s_kpz[it] = kz; }
        if (it == NKP - 1) break;

        // ---- pruned update (f32x2 packed; per-lane == scalar) ----
        float dxc = kx - mt.x, dyc = ky - mt.y, dzc = kz - mt.z;
        float dc = __fsqrt_rn(dxc * dxc + dyc * dyc + dzc * dzc);
        float lhs = dc - mt.w - 1.0e-3f;
        bool changed = !((lhs > 0.0f) && (lhs * lhs * 0.99999f > vm));
        if (changed) {
            ull knx = f2pack(-kx, -kx);
            ull kny = f2pack(-ky, -ky);
            ull knz = f2pack(-kz, -kz);
            float m0 = -3.0e38f, m1 = -3.0e38f;
            #pragma unroll
            for (int q = 0; q < 8; ++q) {
                int ti = q * 1024 + t;
                float2 xq = s_xp[ti], yq = s_yp[ti], zq = s_zp[ti];
                ull dx = f2add(f2pack(xq.x, xq.y), knx);
                ull dy = f2add(f2pack(yq.x, yq.y), kny);
                ull dz = f2add(f2pack(zq.x, zq.y), knz);
                ull d2 = f2mul(dx, dx);
                d2 = f2fma(dy, dy, d2);
                d2 = f2fma(dz, dz, d2);
                float n0, n1; f2unpack(d2, n0, n1);
                float v0 = fminf(dd[2 * q],     n0);
                float v1 = fminf(dd[2 * q + 1], n1);
                dd[2 * q] = v0; dd[2 * q + 1] = v1;
                if (q < 4) { m0 = fmaxf(m0, fmaxf(v0, v1)); }
                else       { m1 = fmaxf(m1, fmaxf(v0, v1)); }
            }
            vm = fmaxf(m0, m1);
            unsigned nbo = 0xffffu; int nbp = 0;
            if (m0 == vm) {
                #pragma unroll
                for (int p = 0; p < 8; ++p)
                    if (dd[p] == vm) {
                        unsigned o = __ldg(perm + 16 * t + p);
                        if (o < nbo) { nbo = o; nbp = p; }
                    }
            }
            if (m1 == vm) {
                #pragma unroll
                for (int p = 8; p < 16; ++p)
                    if (dd[p] == vm) {
                        unsigned o = __ldg(perm + 16 * t + p);
                        if (o < nbo) { nbo = o; nbp = p; }
                    }
            }
            pair = ((ull)fkey(vm) << 32)
                 | ((ull)((0x3fffu - nbo) & 0x3fffu) << 14)
                 | (ull)(16 * t + nbp);
        }
        if (__ballot_sync(FULLM, changed)) {
            unsigned hk = (unsigned)(pair >> 32);
            unsigned wk = __reduce_max_sync(FULLM, hk);
            unsigned lo = (hk == wk) ? (unsigned)pair : 0u;
            lo = __reduce_max_sync(FULLM, lo);
            if (j == 0) s_pairs[w] = ((ull)wk << 32) | lo;
        }
        __syncthreads();                               // the ONLY barrier
    }

    // flush keypoints to global once (coalesced, cooperative)
    __syncthreads();
    for (int i = t; i < NKP; i += 1024) {
        g_kpx[b][i] = s_kpx[i];
        g_kpy[b][i] = s_kpy[i];
        g_kpz[b][i] = s_kpz[i];
    }
}

// ---------------- 5) per-point MLPs -----------------------------------------
__global__ void fraw_kernel(const float* __restrict__ points,
                            const float* __restrict__ W,
                            const float* __restrict__ bias) {
    int tid = blockIdx.x * blockDim.x + threadIdx.x;
    if (tid >= NB * NPTS * CRAW) return;
    int c = tid & (CRAW - 1);
    int pi = tid >> 5;
    const float* p = points + (size_t)pi * 5;
    float v = p[3] * W[c] + p[4] * W[CRAW + c] + bias[c];
    g_fraw[tid] = fmaxf(v, 0.0f);
}

__global__ void fc3_kernel(const float* __restrict__ conv3,
                           const float* __restrict__ W,
                           const float* __restrict__ bias) {
    int tid = blockIdx.x * blockDim.x + threadIdx.x;
    if (tid >= NB * MC3 * CC3) return;
    int c = tid & (CC3 - 1);
    int pi = tid >> 6;
    const float* p = conv3 + (size_t)pi * 67 + 3;
    float acc = 0.0f;
    #pragma unroll 8
    for (int k = 0; k < CC3; ++k) acc += p[k] * W[k * CC3 + c];
    g_fc3[tid] = fmaxf(acc + bias[c], 0.0f);
}

// ---------------- 6) bilinear BEV sampling ----------------------------------
__global__ void bev_kernel(const float* __restrict__ sf) {
    int k = blockIdx.x, b = blockIdx.y, c = threadIdx.x;
    float kx = g_kpx[b][k], ky = g_kpy[b][k];
    float xi = __fdiv_rn(__fdiv_rn(kx - (-75.2f), 0.1f), 8.0f);
    float yi = __fdiv_rn(__fdiv_rn(ky - (-75.2f), 0.1f), 8.0f);
    int x0 = min(max((int)floorf(xi), 0), HW - 1);
    int x1 = min(x0 + 1, HW - 1);
    int y0 = min(max((int)floorf(yi), 0), HW - 1);
    int y1 = min(y0 + 1, HW - 1);
    float xf0 = (float)x0, xf1 = (float)x1, yf0 = (float)y0, yf1 = (float)y1;
    float wa = (xf1 - xi) * (yf1 - yi);
    float wb = (xf1 - xi) * (yi - yf0);
    float wc = (xi - xf0) * (yf1 - yi);
    float wd = (xi - xf0) * (yi - yf0);
    const float* im = sf + ((size_t)b * CBEV + c) * (HW * HW);
    float Ia = im[y0 * HW + x0];
    float Ib = im[y1 * HW + x0];
    float Ic = im[y0 * HW + x1];
    float Id = im[y1 * HW + x1];
    g_feats[((size_t)b * NKP + k) * CF + c] = Ia * wa + Ib * wb + Ic * wc + Id * wd;
}

// ---------------- 7) radius aggregation (ballot-broadcast) ------------------
__global__ void agg_raw_kernel(float r2) {
    int b = blockIdx.y;
    int warp = threadIdx.x >> 5, lane = threadIdx.x & 31;
    int k = blockIdx.x * 8 + warp;
    float kx = g_kpx[b][k], ky = g_kpy[b][k], kz = g_kpz[b][k];
    float acc = 0.0f;
    int cnt = 0;
    __shared__ float sx[256], sy[256], sz[256];
    for (int base = 0; base < NPTS; base += 256) {
        __syncthreads();
        int i = base + threadIdx.x;
        sx[threadIdx.x] = g_px[b][i];
        sy[threadIdx.x] = g_py[b][i];
        sz[threadIdx.x] = g_pz[b][i];
        __syncthreads();
        #pragma unroll
        for (int s = 0; s < 8; ++s) {
            int jj = s * 32 + lane;
            float dx = sx[jj] - kx, dy = sy[jj] - ky, dz = sz[jj] - kz;
            float d2 = dx * dx + dy * dy + dz * dz;
            unsigned m = __ballot_sync(FULLM, d2 < r2);
            while (m) {
                int src = __ffs(m) - 1;
                m &= m - 1;
                int gp = base + s * 32 + src;
                acc += g_fraw[((size_t)b * NPTS + gp) * CRAW + lane];
                cnt++;
            }
        }
    }
    float c = fmaxf((float)cnt, 1.0f);
    g_feats[((size_t)b * NKP + k) * CF + CBEV + lane] = acc / c;
}

__global__ void agg_c3_kernel(float r2) {
    int b = blockIdx.y;
    int warp = threadIdx.x >> 5, lane = threadIdx.x & 31;
    int k = blockIdx.x * 8 + warp;
    float kx = g_kpx[b][k], ky = g_kpy[b][k], kz = g_kpz[b][k];
    float acc0 = 0.0f, acc1 = 0.0f;
    int cnt = 0;
    __shared__ float sx[256], sy[256], sz[256];
    for (int base = 0; base < MC3; base += 256) {
        __syncthreads();
        int i = base + threadIdx.x;
        sx[threadIdx.x] = g_cx[b][i];
        sy[threadIdx.x] = g_cy[b][i];
        sz[threadIdx.x] = g_cz[b][i];
        __syncthreads();
        #pragma unroll
        for (int s = 0; s < 8; ++s) {
            int jj = s * 32 + lane;
            float dx = sx[jj] - kx, dy = sy[jj] - ky, dz = sz[jj] - kz;
            float d2 = dx * dx + dy * dy + dz * dz;
            unsigned m = __ballot_sync(FULLM, d2 < r2);
            while (m) {
                int src = __ffs(m) - 1;
                m &= m - 1;
                int gp = base + s * 32 + src;
                const float* fp = g_fc3 + ((size_t)b * MC3 + gp) * CC3;
                acc0 += fp[lane];
                acc1 += fp[lane + 32];
                cnt++;
            }
        }
    }
    float c = fmaxf((float)cnt, 1.0f);
    float* o = g_feats + ((size_t)b * NKP + k) * CF + CBEV + CRAW;
    o[lane] = acc0 / c;
    o[lane + 32] = acc1 / c;
}

// ---------------- 8) fuse GEMM + BN + ReLU ----------------------------------
#define ROWS_PB 16
__global__ void fuse_kernel(const float* __restrict__ W,
                            const float* __restrict__ gamma,
                            const float* __restrict__ beta,
                            const float* __restrict__ mean,
                            const float* __restrict__ var,
                            float* __restrict__ out) {
    __shared__ float sf[ROWS_PB][CF];
    int row0 = blockIdx.x * ROWS_PB;
    int tid = threadIdx.x;
    for (int idx = tid; idx < ROWS_PB * CF; idx += 128) {
        ((float*)sf)[idx] = g_feats[(size_t)row0 * CF + idx];
    }
    __syncthreads();
    int c = tid;
    float acc[ROWS_PB];
    #pragma unroll
    for (int r = 0; r < ROWS_PB; ++r) acc[r] = 0.0f;
    for (int k = 0; k < CF; ++k) {
        float wv = W[k * COUT + c];
        #pragma unroll
        for (int r = 0; r < ROWS_PB; ++r) acc[r] += sf[r][k] * wv;
    }
    float mu = mean[c];
    float iv = rsqrtf(var[c] + 1e-5f);
    float g = gamma[c], be = beta[c];
    #pragma unroll
    for (int r = 0; r < ROWS_PB; ++r) {
        float v = (acc[r] - mu) * iv * g + be;
        out[(size_t)(row0 + r) * COUT + c] = fmaxf(v, 0.0f);
    }
}

// ---------------- 9) keypoints output ---------------------------------------
__global__ void kpout_kernel(float* __restrict__ out) {
    int tid = blockIdx.x * blockDim.x + threadIdx.x;
    if (tid >= NB * NKP * 3) return;
    int b = tid / (NKP * 3);
    int rem = tid % (NKP * 3);
    int k = rem / 3, d = rem % 3;
    float v = (d == 0) ? g_kpx[b][k] : (d == 1 ? g_kpy[b][k] : g_kpz[b][k]);
    out[(size_t)NB * NKP * COUT + tid] = v;
}

// ---------------- launcher ---------------------------------------------------
extern "C" void kernel_launch(void* const* d_in, const int* in_sizes, int n_in,
                              void* d_out, int out_size) {
    const float* points  = (const float*)d_in[0];
    const float* bboxes  = (const float*)d_in[1];
    const float* spatial = (const float*)d_in[2];
    const float* conv3   = (const float*)d_in[3];
    const float* W_raw   = (const float*)d_in[4];
    const float* b_raw   = (const float*)d_in[5];
    const float* W_c3    = (const float*)d_in[6];
    const float* b_c3    = (const float*)d_in[7];
    const float* W_fuse  = (const float*)d_in[8];
    const float* bn_g    = (const float*)d_in[9];
    const float* bn_b    = (const float*)d_in[10];
    const float* bn_m    = (const float*)d_in[11];
    const float* bn_v    = (const float*)d_in[12];
    float* out = (float*)d_out;

    // coords (192KB) + staged keypoints (24KB)
    const int fps_smem = 3 * NPTS * (int)sizeof(float) + 3 * NKP * (int)sizeof(float);
    cudaFuncSetAttribute(fps_kernel, cudaFuncAttributeMaxDynamicSharedMemorySize,
                         fps_smem);

    prep_points_kernel<<<(NB * NPTS + 255) / 256, 256>>>(points, bboxes);   // 1
    sortprep_kernel<<<NB, 1024>>>();                                        // 2
    prep_c3_kernel<<<(NB * MC3 + 255) / 256, 256>>>(conv3);                 // 3
    fps_kernel<<<NB, 1024, fps_smem>>>();                                   // 4 <- ncu
    fraw_kernel<<<(NB * NPTS * CRAW + 255) / 256, 256>>>(points, W_raw, b_raw);
    fc3_kernel<<<(NB * MC3 * CC3 + 255) / 256, 256>>>(conv3, W_c3, b_c3);
    bev_kernel<<<dim3(NKP, NB), CBEV>>>(spatial);
    agg_raw_kernel<<<dim3(NKP / 8, NB), 256>>>(0.8f * 0.8f);
    agg_c3_kernel<<<dim3(NKP / 8, NB), 256>>>(1.6f * 1.6f);
    fuse_kernel<<<(NB * NKP) / ROWS_PB, COUT>>>(W_fuse, bn_g, bn_b, bn_m, bn_v, out);
    kpout_kernel<<<(NB * NKP * 3 + 255) / 256, 256>>>(out);
}